// round 2
// baseline (speedup 1.0000x reference)
#include <cuda_runtime.h>
#include <math.h>

#define N0 50000
#define N1 12500
#define N2 3125
#define E0C 800000
#define E1C 200000
#define E2C 50000
#define NNZC 200000

// ---------------- scratch (allocation-free: __device__ globals) ----------------
__device__ float g_agg6[N0 * 6];
__device__ float g_agg [N0 * 128];
__device__ float g_h1  [N0 * 128];
__device__ float g_h2  [N0 * 128];
__device__ float g_e0  [N0 * 96];
__device__ float g_e1  [N1 * 96];
__device__ float g_e2  [N2 * 96];
__device__ float g_i1  [N0 * 96];
__device__ float g_i2  [N0 * 96];
// CSR machinery
__device__ int   g_cnt [N0];
__device__ int   g_off [N0 + 1];
__device__ int   g_cur [N0];
__device__ int   g_slots[E0C];     // max(E, NNZ) <= 800000
__device__ float g_slotv[NNZC];

static inline int cdiv(int a, int b) { return (a + b - 1) / b; }

// ---------------- CSR build ----------------

__global__ void zero_int_kernel(int* __restrict__ p, int n) {
    int i = (blockIdx.x * blockDim.x + threadIdx.x) * 4;
    if (i + 3 < n) { *(int4*)(p + i) = make_int4(0, 0, 0, 0); }
    else { for (int j = i; j < n; j++) p[j] = 0; }
}

__global__ void count_kernel(const int* __restrict__ idx, int E, int* __restrict__ cnt) {
    int e = blockIdx.x * blockDim.x + threadIdx.x;
    if (e < E) atomicAdd(&cnt[idx[e]], 1);
}

// single-block exclusive scan over cnt[0..n) -> off[0..n], cur = off
__global__ void scan_kernel(const int* __restrict__ cnt, int* __restrict__ off,
                            int* __restrict__ cur, int n) {
    __shared__ int part[1024];
    int t = threadIdx.x;
    int chunk = (n + 1023) / 1024;
    int beg = t * chunk;
    int end = beg + chunk; if (end > n) end = n;
    int s = 0;
    for (int i = beg; i < end; i++) s += cnt[i];
    part[t] = s;
    __syncthreads();
    for (int d = 1; d < 1024; d <<= 1) {
        int v = (t >= d) ? part[t - d] : 0;
        __syncthreads();
        part[t] += v;
        __syncthreads();
    }
    int run = (t == 0) ? 0 : part[t - 1];
    for (int i = beg; i < end; i++) {
        off[i] = run; cur[i] = run;
        run += cnt[i];
    }
    if (t == 1023) off[n] = part[1023];
}

// graph edges: slot[pos] = src, binned by dst
__global__ void fill_kernel(const int* __restrict__ ei, int E,
                            int* __restrict__ cur, int* __restrict__ slots) {
    int e = blockIdx.x * blockDim.x + threadIdx.x;
    if (e >= E) return;
    int s = ei[e];
    int d = ei[E + e];
    int pos = atomicAdd(&cur[d], 1);
    slots[pos] = s;
}

// interp nnz: (col, val) binned by row
__global__ void fill_iv_kernel(const int* __restrict__ rows, const int* __restrict__ cols,
                               const float* __restrict__ vals, int nnz,
                               int* __restrict__ cur, int* __restrict__ slotc,
                               float* __restrict__ slotv) {
    int e = blockIdx.x * blockDim.x + threadIdx.x;
    if (e >= nnz) return;
    int pos = atomicAdd(&cur[rows[e]], 1);
    slotc[pos] = cols[e];
    slotv[pos] = vals[e];
}

// ---------------- gathers (replace all float atomics) ----------------

// agg6[w] = sum over edges of x[src] (6 features); thread per node
__global__ void gather6_kernel(const float* __restrict__ x, const int* __restrict__ off,
                               const int* __restrict__ cnt, const int* __restrict__ slots,
                               float* __restrict__ agg6, int n) {
    int w = blockIdx.x * blockDim.x + threadIdx.x;
    if (w >= n) return;
    int o = off[w], deg = cnt[w];
    float a[6] = {0.f, 0.f, 0.f, 0.f, 0.f, 0.f};
    for (int e = 0; e < deg; e++) {
        int s = slots[o + e];
#pragma unroll
        for (int j = 0; j < 6; j++) a[j] += x[s * 6 + j];
    }
#pragma unroll
    for (int j = 0; j < 6; j++) agg6[w * 6 + j] = a[j];
}

// agg[w] = sum over edges of h[src] (128 features); warp per node, lane -> 4 feats
__global__ void gather128_kernel(const float* __restrict__ h, const int* __restrict__ off,
                                 const int* __restrict__ cnt, const int* __restrict__ slots,
                                 float* __restrict__ agg, int n) {
    int w = (blockIdx.x * blockDim.x + threadIdx.x) >> 5;
    int lane = threadIdx.x & 31;
    if (w >= n) return;
    int o = off[w], deg = cnt[w];
    float4 acc = make_float4(0.f, 0.f, 0.f, 0.f);
    for (int e = 0; e < deg; e++) {
        int s = slots[o + e];
        float4 v = *(const float4*)(h + (size_t)s * 128 + lane * 4);
        acc.x += v.x; acc.y += v.y; acc.z += v.z; acc.w += v.w;
    }
    *(float4*)(agg + (size_t)w * 128 + lane * 4) = acc;
}

// out[w] = sum over nnz of val * e[col] (96 features); warp per node, lanes 0..23
__global__ void gatherI_kernel(const float* __restrict__ e, const int* __restrict__ off,
                               const int* __restrict__ cnt, const int* __restrict__ slotc,
                               const float* __restrict__ slotv, float* __restrict__ out, int n) {
    int w = (blockIdx.x * blockDim.x + threadIdx.x) >> 5;
    int lane = threadIdx.x & 31;
    if (w >= n) return;
    int o = off[w], deg = cnt[w];
    float4 acc = make_float4(0.f, 0.f, 0.f, 0.f);
    for (int j = 0; j < deg; j++) {
        int c = slotc[o + j];
        float v = slotv[o + j];
        if (lane < 24) {
            float4 x = *(const float4*)(e + (size_t)c * 96 + lane * 4);
            acc.x = fmaf(v, x.x, acc.x);
            acc.y = fmaf(v, x.y, acc.y);
            acc.z = fmaf(v, x.z, acc.z);
            acc.w = fmaf(v, x.w, acc.w);
        }
    }
    if (lane < 24)
        *(float4*)(out + (size_t)w * 96 + lane * 4) = acc;
}

// ---------------- dense kernels ----------------

// h1 = relu(agg6 @ Wrel(6x128) + brel + x @ Wroot(6x128)); block=128 thr, 32 nodes/block
__global__ void conv1_kernel(const float* __restrict__ x, const float* __restrict__ agg6,
                             const float* __restrict__ Wrel, const float* __restrict__ brel,
                             const float* __restrict__ Wroot, float* __restrict__ h1, int n) {
    __shared__ float sx[32 * 6];
    __shared__ float sa[32 * 6];
    int base = blockIdx.x * 32;
    int cnt = n - base; if (cnt > 32) cnt = 32;
    int t = threadIdx.x;
    for (int idx = t; idx < cnt * 6; idx += 128) {
        sx[idx] = x[base * 6 + idx];
        sa[idx] = agg6[base * 6 + idx];
    }
    __syncthreads();
    float wrel[6], wroot[6];
#pragma unroll
    for (int k = 0; k < 6; k++) { wrel[k] = Wrel[k * 128 + t]; wroot[k] = Wroot[k * 128 + t]; }
    float b = brel[t];
    for (int j = 0; j < cnt; j++) {
        float acc = b;
#pragma unroll
        for (int k = 0; k < 6; k++)
            acc = fmaf(sa[j * 6 + k], wrel[k], fmaf(sx[j * 6 + k], wroot[k], acc));
        h1[(base + j) * 128 + t] = fmaxf(acc, 0.f);
    }
}

// out = relu(in1 @ W1(128x128) + b + in2 @ W2(128x128))
__global__ void __launch_bounds__(256) conv2_kernel(
    const float* __restrict__ in1, const float* __restrict__ in2,
    const float* __restrict__ W1, const float* __restrict__ W2,
    const float* __restrict__ b, float* __restrict__ out, int n) {
    extern __shared__ float smem[];
    float* s1 = smem;           // [128][128]
    float* s2 = smem + 16384;   // [128][128]
    int base = blockIdx.x * 128;
    int cnt = n - base; if (cnt > 128) cnt = 128;
    int t = threadIdx.x;
    for (int idx = t * 4; idx < cnt * 128; idx += 256 * 4) {
        *(float4*)(s1 + idx) = *(const float4*)(in1 + (size_t)base * 128 + idx);
        *(float4*)(s2 + idx) = *(const float4*)(in2 + (size_t)base * 128 + idx);
    }
    __syncthreads();
    int warp = t >> 5, lane = t & 31;
    int f = lane * 4;
    int nb = warp * 16;
    float4 bias = *(const float4*)(b + f);
    float acc[16][4];
#pragma unroll
    for (int j = 0; j < 16; j++) {
        acc[j][0] = bias.x; acc[j][1] = bias.y; acc[j][2] = bias.z; acc[j][3] = bias.w;
    }
    for (int k = 0; k < 128; k++) {
        float4 w1 = *(const float4*)(W1 + k * 128 + f);
        float4 w2 = *(const float4*)(W2 + k * 128 + f);
#pragma unroll
        for (int j = 0; j < 16; j++) {
            float a1 = s1[(nb + j) * 128 + k];
            float a2 = s2[(nb + j) * 128 + k];
            acc[j][0] = fmaf(a1, w1.x, fmaf(a2, w2.x, acc[j][0]));
            acc[j][1] = fmaf(a1, w1.y, fmaf(a2, w2.y, acc[j][1]));
            acc[j][2] = fmaf(a1, w1.z, fmaf(a2, w2.z, acc[j][2]));
            acc[j][3] = fmaf(a1, w1.w, fmaf(a2, w2.w, acc[j][3]));
        }
    }
#pragma unroll
    for (int j = 0; j < 16; j++) {
        int node = nb + j;
        if (node < cnt) {
            float4 r;
            r.x = fmaxf(acc[j][0], 0.f);
            r.y = fmaxf(acc[j][1], 0.f);
            r.z = fmaxf(acc[j][2], 0.f);
            r.w = fmaxf(acc[j][3], 0.f);
            *(float4*)(out + (size_t)(base + node) * 128 + f) = r;
        }
    }
}

// out = in @ W(128x96) + b
__global__ void __launch_bounds__(256) lin_kernel(
    const float* __restrict__ in, const float* __restrict__ W,
    const float* __restrict__ b, float* __restrict__ out, int n) {
    extern __shared__ float smem[];  // [128][128]
    int base = blockIdx.x * 128;
    int cnt = n - base; if (cnt > 128) cnt = 128;
    int t = threadIdx.x;
    for (int idx = t * 4; idx < cnt * 128; idx += 256 * 4)
        *(float4*)(smem + idx) = *(const float4*)(in + (size_t)base * 128 + idx);
    __syncthreads();
    int warp = t >> 5, lane = t & 31;
    int f = lane * 4;
    int nb = warp * 16;
    if (f < 96) {
        float4 bias = *(const float4*)(b + f);
        float acc[16][4];
#pragma unroll
        for (int j = 0; j < 16; j++) {
            acc[j][0] = bias.x; acc[j][1] = bias.y; acc[j][2] = bias.z; acc[j][3] = bias.w;
        }
        for (int k = 0; k < 128; k++) {
            float4 w = *(const float4*)(W + k * 96 + f);
#pragma unroll
            for (int j = 0; j < 16; j++) {
                float a = smem[(nb + j) * 128 + k];
                acc[j][0] = fmaf(a, w.x, acc[j][0]);
                acc[j][1] = fmaf(a, w.y, acc[j][1]);
                acc[j][2] = fmaf(a, w.z, acc[j][2]);
                acc[j][3] = fmaf(a, w.w, acc[j][3]);
            }
        }
#pragma unroll
        for (int j = 0; j < 16; j++) {
            int node = nb + j;
            if (node < cnt) {
                float4 r = make_float4(acc[j][0], acc[j][1], acc[j][2], acc[j][3]);
                *(float4*)(out + (size_t)(base + node) * 96 + f) = r;
            }
        }
    }
}

// decoder as GEMM: tile 128 nodes, per branch: stage [128][96] input in smem,
// warp -> 16 nodes, lane -> 2 of 64 hidden; elu; dot with Wout; warp-reduce
__global__ void __launch_bounds__(256) dec_gemm_kernel(
    const float* __restrict__ e0, const float* __restrict__ i1,
    const float* __restrict__ i2,
    const float* __restrict__ W0, const float* __restrict__ b0,
    const float* __restrict__ Wout, const float* __restrict__ bout,
    float* __restrict__ out, int n) {
    extern __shared__ float sin_[]; // [128][96]
    int base = blockIdx.x * 128;
    int cnt = n - base; if (cnt > 128) cnt = 128;
    int t = threadIdx.x;
    int warp = t >> 5, lane = t & 31;
    int nb = warp * 16;
#pragma unroll
    for (int br = 0; br < 3; br++) {
        __syncthreads();  // protect previous branch's smem reads
        for (int idx = t; idx < cnt * 24; idx += 256) {
            int node = idx / 24, q = idx % 24;
            const float* srcp =
                (q < 8)  ? (e0 + (size_t)(base + node) * 96 + br * 32 + q * 4) :
                (q < 16) ? (i1 + (size_t)(base + node) * 96 + br * 32 + (q - 8) * 4) :
                           (i2 + (size_t)(base + node) * 96 + br * 32 + (q - 16) * 4);
            *(float4*)(sin_ + node * 96 + q * 4) = *(const float4*)srcp;
        }
        __syncthreads();
        const float* W = W0 + br * 96 * 64;
        float2 bb = *(const float2*)(b0 + br * 64 + 2 * lane);
        float acc0[16], acc1[16];
#pragma unroll
        for (int j = 0; j < 16; j++) { acc0[j] = bb.x; acc1[j] = bb.y; }
        for (int k = 0; k < 96; k += 4) {
            float2 w0 = *(const float2*)(W + (k + 0) * 64 + 2 * lane);
            float2 w1 = *(const float2*)(W + (k + 1) * 64 + 2 * lane);
            float2 w2 = *(const float2*)(W + (k + 2) * 64 + 2 * lane);
            float2 w3 = *(const float2*)(W + (k + 3) * 64 + 2 * lane);
#pragma unroll
            for (int j = 0; j < 16; j++) {
                float4 a = *(const float4*)(sin_ + (nb + j) * 96 + k);
                acc0[j] = fmaf(a.x, w0.x, acc0[j]); acc1[j] = fmaf(a.x, w0.y, acc1[j]);
                acc0[j] = fmaf(a.y, w1.x, acc0[j]); acc1[j] = fmaf(a.y, w1.y, acc1[j]);
                acc0[j] = fmaf(a.z, w2.x, acc0[j]); acc1[j] = fmaf(a.z, w2.y, acc1[j]);
                acc0[j] = fmaf(a.w, w3.x, acc0[j]); acc1[j] = fmaf(a.w, w3.y, acc1[j]);
            }
        }
        float2 wo = *(const float2*)(Wout + br * 64 + 2 * lane);
        float bo = bout[br];
#pragma unroll
        for (int j = 0; j < 16; j++) {
            float h0 = acc0[j] > 0.f ? acc0[j] : expm1f(acc0[j]);
            float h1 = acc1[j] > 0.f ? acc1[j] : expm1f(acc1[j]);
            float r = fmaf(h0, wo.x, h1 * wo.y);
#pragma unroll
            for (int s = 16; s > 0; s >>= 1)
                r += __shfl_xor_sync(0xffffffffu, r, s);
            if (lane == 0 && nb + j < cnt)
                out[(size_t)(base + nb + j) * 3 + br] = r + bo;
        }
    }
}

// ---------------- host orchestration ----------------

extern "C" void kernel_launch(void* const* d_in, const int* in_sizes, int n_in,
                              void* d_out, int out_size) {
    const float* x[3]  = { (const float*)d_in[0], (const float*)d_in[1], (const float*)d_in[2] };
    const int*   ei[3] = { (const int*)d_in[3], (const int*)d_in[4], (const int*)d_in[5] };
    const int*   A1r = (const int*)d_in[6];
    const int*   A1c = (const int*)d_in[7];
    const float* A1v = (const float*)d_in[8];
    const int*   A2r = (const int*)d_in[9];
    const int*   A2c = (const int*)d_in[10];
    const float* A2v = (const float*)d_in[11];
    const float* c1Wrel  = (const float*)d_in[12];
    const float* c1brel  = (const float*)d_in[13];
    const float* c1Wroot = (const float*)d_in[14];
    const float* c2Wrel  = (const float*)d_in[15];
    const float* c2brel  = (const float*)d_in[16];
    const float* c2Wroot = (const float*)d_in[17];
    const float* linW = (const float*)d_in[18];
    const float* linb = (const float*)d_in[19];
    const float* dW0   = (const float*)d_in[20];
    const float* db0   = (const float*)d_in[21];
    const float* dWout = (const float*)d_in[22];
    const float* dbout = (const float*)d_in[23];
    float* out = (float*)d_out;

    void* p;
    cudaGetSymbolAddress(&p, g_agg6);  float* agg6  = (float*)p;
    cudaGetSymbolAddress(&p, g_agg);   float* agg   = (float*)p;
    cudaGetSymbolAddress(&p, g_h1);    float* h1    = (float*)p;
    cudaGetSymbolAddress(&p, g_h2);    float* h2    = (float*)p;
    cudaGetSymbolAddress(&p, g_e0);    float* e0    = (float*)p;
    cudaGetSymbolAddress(&p, g_e1);    float* e1    = (float*)p;
    cudaGetSymbolAddress(&p, g_e2);    float* e2    = (float*)p;
    cudaGetSymbolAddress(&p, g_i1);    float* i1b   = (float*)p;
    cudaGetSymbolAddress(&p, g_i2);    float* i2b   = (float*)p;
    cudaGetSymbolAddress(&p, g_cnt);   int*   cnt   = (int*)p;
    cudaGetSymbolAddress(&p, g_off);   int*   off   = (int*)p;
    cudaGetSymbolAddress(&p, g_cur);   int*   cur   = (int*)p;
    cudaGetSymbolAddress(&p, g_slots); int*   slots = (int*)p;
    cudaGetSymbolAddress(&p, g_slotv); float* slotv = (float*)p;

    cudaFuncSetAttribute(conv2_kernel, cudaFuncAttributeMaxDynamicSharedMemorySize, 131072);
    cudaFuncSetAttribute(lin_kernel,   cudaFuncAttributeMaxDynamicSharedMemorySize, 65536);
    cudaFuncSetAttribute(dec_gemm_kernel, cudaFuncAttributeMaxDynamicSharedMemorySize, 49152);

    const int ncnt[3] = { N0, N1, N2 };
    const int ecnt[3] = { E0C, E1C, E2C };
    float* evec[3] = { e0, e1, e2 };

    for (int i = 0; i < 3; i++) {
        int n = ncnt[i], E = ecnt[i];
        // CSR build (binned by dst)
        zero_int_kernel<<<cdiv(cdiv(n, 4), 256), 256>>>(cnt, n);
        count_kernel<<<cdiv(E, 256), 256>>>(ei[i] + E, E, cnt);   // dst = ei[1]
        scan_kernel<<<1, 1024>>>(cnt, off, cur, n);
        fill_kernel<<<cdiv(E, 256), 256>>>(ei[i], E, cur, slots);
        // layer 1
        gather6_kernel<<<cdiv(n, 256), 256>>>(x[i], off, cnt, slots, agg6, n);
        conv1_kernel<<<cdiv(n, 32), 128>>>(x[i], agg6,
                                           c1Wrel + i * 6 * 128, c1brel + i * 128,
                                           c1Wroot + i * 6 * 128, h1, n);
        // layer 2
        gather128_kernel<<<cdiv(n * 32, 256), 256>>>(h1, off, cnt, slots, agg, n);
        conv2_kernel<<<cdiv(n, 128), 256, 131072>>>(agg, h1,
                                                    c2Wrel + i * 128 * 128,
                                                    c2Wroot + i * 128 * 128,
                                                    c2brel + i * 128, h2, n);
        lin_kernel<<<cdiv(n, 128), 256, 65536>>>(h2, linW + i * 128 * 96,
                                                 linb + i * 96, evec[i], n);
    }

    // interpolation: CSR by rows, then gather
    zero_int_kernel<<<cdiv(cdiv(N0, 4), 256), 256>>>(cnt, N0);
    count_kernel<<<cdiv(NNZC, 256), 256>>>(A1r, NNZC, cnt);
    scan_kernel<<<1, 1024>>>(cnt, off, cur, N0);
    fill_iv_kernel<<<cdiv(NNZC, 256), 256>>>(A1r, A1c, A1v, NNZC, cur, slots, slotv);
    gatherI_kernel<<<cdiv(N0 * 32, 256), 256>>>(e1, off, cnt, slots, slotv, i1b, N0);

    zero_int_kernel<<<cdiv(cdiv(N0, 4), 256), 256>>>(cnt, N0);
    count_kernel<<<cdiv(NNZC, 256), 256>>>(A2r, NNZC, cnt);
    scan_kernel<<<1, 1024>>>(cnt, off, cur, N0);
    fill_iv_kernel<<<cdiv(NNZC, 256), 256>>>(A2r, A2c, A2v, NNZC, cur, slots, slotv);
    gatherI_kernel<<<cdiv(N0 * 32, 256), 256>>>(e2, off, cnt, slots, slotv, i2b, N0);

    dec_gemm_kernel<<<cdiv(N0, 128), 256, 49152>>>(e0, i1b, i2b, dW0, db0,
                                                   dWout, dbout, out, N0);
}

// round 3
// speedup vs baseline: 1.4822x; 1.4822x over previous
#include <cuda_runtime.h>
#include <math.h>

#define N0 50000
#define N1 12500
#define N2 3125
#define NTOT 65625            // N0+N1+N2
#define E0C 800000
#define E1C 200000
#define E2C 50000
#define ETOT 1050000
#define NNZC 200000

// node row offsets per level
#define NB1 50000
#define NB2 62500
// edge offsets
#define EB1 800000
#define EB2 1000000

// -------- fused zeroed scratch region: [agg6 | agg | i1 | i2] --------
#define AGG6_OFF 0
#define AGG6_SZ  393752        // 65625*6 padded to %4
#define AGG_OFF  393752
#define AGG_SZ   8400000       // 65625*128
#define I1_OFF   8793752
#define I1_SZ    4800000       // 50000*96
#define I2_OFF   13593752
#define I2_SZ    4800000
#define ZR_TOT   18393752

__device__ float g_zr[ZR_TOT];
__device__ float g_h1[NTOT * 128];
__device__ float g_h2[NTOT * 128];
__device__ float g_e [NTOT * 96];

static inline int cdiv(int a, int b) { return (a + b - 1) / b; }

// ---------------- kernels ----------------

__global__ void zero4_kernel(float4* __restrict__ p, int nq) {
    int i = blockIdx.x * blockDim.x + threadIdx.x;
    if (i < nq) p[i] = make_float4(0.f, 0.f, 0.f, 0.f);
}

// stage 1 aggregation, all levels: agg6[dst] += x[src] (6 feats)
__global__ void scatter6_all(const float* __restrict__ x0, const float* __restrict__ x1,
                             const float* __restrict__ x2,
                             const int* __restrict__ ei0, const int* __restrict__ ei1,
                             const int* __restrict__ ei2,
                             float* __restrict__ agg6) {
    int e = blockIdx.x * blockDim.x + threadIdx.x;
    if (e >= ETOT) return;
    int lvl = (e >= EB1) + (e >= EB2);
    const int* ei;
    const float* x;
    int le, E, nb;
    if (lvl == 0)      { ei = ei0; x = x0; le = e;       E = E0C; nb = 0;   }
    else if (lvl == 1) { ei = ei1; x = x1; le = e - EB1; E = E1C; nb = NB1; }
    else               { ei = ei2; x = x2; le = e - EB2; E = E2C; nb = NB2; }
    int s = ei[le];
    int d = ei[E + le];
    const float* xs = x + (size_t)s * 6;
    float* a = agg6 + (size_t)(nb + d) * 6;
#pragma unroll
    for (int j = 0; j < 6; j++) atomicAdd(&a[j], xs[j]);
}

// conv1, all levels: h1 = relu(agg6 @ Wrel + brel + x @ Wroot); 32 nodes/block
#define C1_B0 1563
#define C1_B1 1954    // 1563 + 391
__global__ void conv1_all(const float* __restrict__ x0, const float* __restrict__ x1,
                          const float* __restrict__ x2,
                          const float* __restrict__ agg6,
                          const float* __restrict__ Wrel, const float* __restrict__ brel,
                          const float* __restrict__ Wroot, float* __restrict__ h1) {
    __shared__ float sx[32 * 6];
    __shared__ float sa[32 * 6];
    int b = blockIdx.x;
    int lvl = (b >= C1_B0) + (b >= C1_B1);
    const float* x;
    int tb, nlv, nb;
    if (lvl == 0)      { x = x0; tb = 0;     nlv = N0; nb = 0;   }
    else if (lvl == 1) { x = x1; tb = C1_B0; nlv = N1; nb = NB1; }
    else               { x = x2; tb = C1_B1; nlv = N2; nb = NB2; }
    int base = (b - tb) * 32;
    int cnt = nlv - base; if (cnt > 32) cnt = 32;
    int t = threadIdx.x;
    for (int idx = t; idx < cnt * 6; idx += 128) {
        sx[idx] = x[(size_t)base * 6 + idx];
        sa[idx] = agg6[(size_t)(nb + base) * 6 + idx];
    }
    __syncthreads();
    const float* Wr = Wrel + lvl * 6 * 128;
    const float* Wo = Wroot + lvl * 6 * 128;
    float wrel[6], wroot[6];
#pragma unroll
    for (int k = 0; k < 6; k++) { wrel[k] = Wr[k * 128 + t]; wroot[k] = Wo[k * 128 + t]; }
    float bb = brel[lvl * 128 + t];
    for (int j = 0; j < cnt; j++) {
        float acc = bb;
#pragma unroll
        for (int k = 0; k < 6; k++)
            acc = fmaf(sa[j * 6 + k], wrel[k], fmaf(sx[j * 6 + k], wroot[k], acc));
        h1[(size_t)(nb + base + j) * 128 + t] = fmaxf(acc, 0.f);
    }
}

// stage 2 aggregation, all levels: agg[dst] += h1[src] (128 feats); warp/edge
__global__ void scatter128_all(const float* __restrict__ h1,
                               const int* __restrict__ ei0, const int* __restrict__ ei1,
                               const int* __restrict__ ei2,
                               float* __restrict__ agg) {
    int w = (blockIdx.x * blockDim.x + threadIdx.x) >> 5;
    int lane = threadIdx.x & 31;
    if (w >= ETOT) return;
    int lvl = (w >= EB1) + (w >= EB2);
    const int* ei;
    int le, E, nb;
    if (lvl == 0)      { ei = ei0; le = w;       E = E0C; nb = 0;   }
    else if (lvl == 1) { ei = ei1; le = w - EB1; E = E1C; nb = NB1; }
    else               { ei = ei2; le = w - EB2; E = E2C; nb = NB2; }
    int s = ei[le];
    int d = ei[E + le];
    float4 v = *(const float4*)(h1 + (size_t)(nb + s) * 128 + lane * 4);
    atomicAdd((float4*)(agg + (size_t)(nb + d) * 128 + lane * 4), v);
}

// conv2, all levels: h2 = relu(agg @ W1 + b + h1 @ W2); 128-node tiles
#define C2_B0 391
#define C2_B1 489     // 391 + 98
__global__ void __launch_bounds__(256) conv2_all(
    const float* __restrict__ agg, const float* __restrict__ h1,
    const float* __restrict__ W1b, const float* __restrict__ W2b,
    const float* __restrict__ bb, float* __restrict__ h2) {
    extern __shared__ float smem[];
    float* s1 = smem;           // [128][128]
    float* s2 = smem + 16384;
    int b = blockIdx.x;
    int lvl = (b >= C2_B0) + (b >= C2_B1);
    int tb, nlv, nb;
    if (lvl == 0)      { tb = 0;     nlv = N0; nb = 0;   }
    else if (lvl == 1) { tb = C2_B0; nlv = N1; nb = NB1; }
    else               { tb = C2_B1; nlv = N2; nb = NB2; }
    int base = (b - tb) * 128;
    int cnt = nlv - base; if (cnt > 128) cnt = 128;
    size_t row0 = (size_t)(nb + base) * 128;
    int t = threadIdx.x;
    for (int idx = t * 4; idx < cnt * 128; idx += 256 * 4) {
        *(float4*)(s1 + idx) = *(const float4*)(agg + row0 + idx);
        *(float4*)(s2 + idx) = *(const float4*)(h1 + row0 + idx);
    }
    __syncthreads();
    const float* W1 = W1b + lvl * 16384;
    const float* W2 = W2b + lvl * 16384;
    int warp = t >> 5, lane = t & 31;
    int f = lane * 4;
    int nbk = warp * 16;
    float4 bias = *(const float4*)(bb + lvl * 128 + f);
    float acc[16][4];
#pragma unroll
    for (int j = 0; j < 16; j++) {
        acc[j][0] = bias.x; acc[j][1] = bias.y; acc[j][2] = bias.z; acc[j][3] = bias.w;
    }
    for (int k = 0; k < 128; k++) {
        float4 w1 = *(const float4*)(W1 + k * 128 + f);
        float4 w2 = *(const float4*)(W2 + k * 128 + f);
#pragma unroll
        for (int j = 0; j < 16; j++) {
            float a1 = s1[(nbk + j) * 128 + k];
            float a2 = s2[(nbk + j) * 128 + k];
            acc[j][0] = fmaf(a1, w1.x, fmaf(a2, w2.x, acc[j][0]));
            acc[j][1] = fmaf(a1, w1.y, fmaf(a2, w2.y, acc[j][1]));
            acc[j][2] = fmaf(a1, w1.z, fmaf(a2, w2.z, acc[j][2]));
            acc[j][3] = fmaf(a1, w1.w, fmaf(a2, w2.w, acc[j][3]));
        }
    }
#pragma unroll
    for (int j = 0; j < 16; j++) {
        if (nbk + j < cnt) {
            float4 r;
            r.x = fmaxf(acc[j][0], 0.f);
            r.y = fmaxf(acc[j][1], 0.f);
            r.z = fmaxf(acc[j][2], 0.f);
            r.w = fmaxf(acc[j][3], 0.f);
            *(float4*)(h2 + row0 + (size_t)(nbk + j) * 128 + f) = r;
        }
    }
}

// lin, all levels: e = h2 @ W(128x96) + b
__global__ void __launch_bounds__(256) lin_all(
    const float* __restrict__ h2, const float* __restrict__ Wb,
    const float* __restrict__ bb, float* __restrict__ e) {
    extern __shared__ float smem[];   // [128][128]
    int b = blockIdx.x;
    int lvl = (b >= C2_B0) + (b >= C2_B1);
    int tb, nlv, nb;
    if (lvl == 0)      { tb = 0;     nlv = N0; nb = 0;   }
    else if (lvl == 1) { tb = C2_B0; nlv = N1; nb = NB1; }
    else               { tb = C2_B1; nlv = N2; nb = NB2; }
    int base = (b - tb) * 128;
    int cnt = nlv - base; if (cnt > 128) cnt = 128;
    size_t row0 = (size_t)(nb + base) * 128;
    int t = threadIdx.x;
    for (int idx = t * 4; idx < cnt * 128; idx += 256 * 4)
        *(float4*)(smem + idx) = *(const float4*)(h2 + row0 + idx);
    __syncthreads();
    int warp = t >> 5, lane = t & 31;
    int f = lane * 4;
    int nbk = warp * 16;
    if (f < 96) {
        const float* W = Wb + lvl * 128 * 96;
        float4 bias = *(const float4*)(bb + lvl * 96 + f);
        float acc[16][4];
#pragma unroll
        for (int j = 0; j < 16; j++) {
            acc[j][0] = bias.x; acc[j][1] = bias.y; acc[j][2] = bias.z; acc[j][3] = bias.w;
        }
        for (int k = 0; k < 128; k++) {
            float4 w = *(const float4*)(W + k * 96 + f);
#pragma unroll
            for (int j = 0; j < 16; j++) {
                float a = smem[(nbk + j) * 128 + k];
                acc[j][0] = fmaf(a, w.x, acc[j][0]);
                acc[j][1] = fmaf(a, w.y, acc[j][1]);
                acc[j][2] = fmaf(a, w.z, acc[j][2]);
                acc[j][3] = fmaf(a, w.w, acc[j][3]);
            }
        }
#pragma unroll
        for (int j = 0; j < 16; j++) {
            if (nbk + j < cnt) {
                float4 r = make_float4(acc[j][0], acc[j][1], acc[j][2], acc[j][3]);
                *(float4*)(e + (size_t)(nb + base + nbk + j) * 96 + f) = r;
            }
        }
    }
}

// both interpolations fused: i{1,2}[row] += val * e{1,2}[col]; warp/nnz, lanes 0..23
__global__ void interp_both(const float* __restrict__ e,
                            const int* __restrict__ A1r, const int* __restrict__ A1c,
                            const float* __restrict__ A1v,
                            const int* __restrict__ A2r, const int* __restrict__ A2c,
                            const float* __restrict__ A2v,
                            float* __restrict__ i1, float* __restrict__ i2) {
    int w = (blockIdx.x * blockDim.x + threadIdx.x) >> 5;
    int lane = threadIdx.x & 31;
    if (w >= 2 * NNZC || lane >= 24) return;
    int r, c; float v; const float* src; float* dst;
    if (w < NNZC) { r = A1r[w]; c = A1c[w]; v = A1v[w];
                    src = e + (size_t)(NB1 + c) * 96; dst = i1; }
    else { int u = w - NNZC; r = A2r[u]; c = A2c[u]; v = A2v[u];
           src = e + (size_t)(NB2 + c) * 96; dst = i2; }
    float4 x = *(const float4*)(src + lane * 4);
    float4 y = make_float4(x.x * v, x.y * v, x.z * v, x.w * v);
    atomicAdd((float4*)(dst + (size_t)r * 96 + lane * 4), y);
}

// decoder as GEMM: tile 128 nodes; per branch stage [128][96] smem; warp->16 nodes
__global__ void __launch_bounds__(256) dec_gemm_kernel(
    const float* __restrict__ e0, const float* __restrict__ i1,
    const float* __restrict__ i2,
    const float* __restrict__ W0, const float* __restrict__ b0,
    const float* __restrict__ Wout, const float* __restrict__ bout,
    float* __restrict__ out, int n) {
    extern __shared__ float sin_[]; // [128][96]
    int base = blockIdx.x * 128;
    int cnt = n - base; if (cnt > 128) cnt = 128;
    int t = threadIdx.x;
    int lane = t & 31;
    int nb = (t >> 5) * 16;
#pragma unroll
    for (int br = 0; br < 3; br++) {
        __syncthreads();
        for (int idx = t; idx < cnt * 24; idx += 256) {
            int node = idx / 24, q = idx % 24;
            const float* srcp =
                (q < 8)  ? (e0 + (size_t)(base + node) * 96 + br * 32 + q * 4) :
                (q < 16) ? (i1 + (size_t)(base + node) * 96 + br * 32 + (q - 8) * 4) :
                           (i2 + (size_t)(base + node) * 96 + br * 32 + (q - 16) * 4);
            *(float4*)(sin_ + node * 96 + q * 4) = *(const float4*)srcp;
        }
        __syncthreads();
        const float* W = W0 + br * 96 * 64;
        float2 bb = *(const float2*)(b0 + br * 64 + 2 * lane);
        float acc0[16], acc1[16];
#pragma unroll
        for (int j = 0; j < 16; j++) { acc0[j] = bb.x; acc1[j] = bb.y; }
        for (int k = 0; k < 96; k += 4) {
            float2 w0 = *(const float2*)(W + (k + 0) * 64 + 2 * lane);
            float2 w1 = *(const float2*)(W + (k + 1) * 64 + 2 * lane);
            float2 w2 = *(const float2*)(W + (k + 2) * 64 + 2 * lane);
            float2 w3 = *(const float2*)(W + (k + 3) * 64 + 2 * lane);
#pragma unroll
            for (int j = 0; j < 16; j++) {
                float4 a = *(const float4*)(sin_ + (nb + j) * 96 + k);
                acc0[j] = fmaf(a.x, w0.x, acc0[j]); acc1[j] = fmaf(a.x, w0.y, acc1[j]);
                acc0[j] = fmaf(a.y, w1.x, acc0[j]); acc1[j] = fmaf(a.y, w1.y, acc1[j]);
                acc0[j] = fmaf(a.z, w2.x, acc0[j]); acc1[j] = fmaf(a.z, w2.y, acc1[j]);
                acc0[j] = fmaf(a.w, w3.x, acc0[j]); acc1[j] = fmaf(a.w, w3.y, acc1[j]);
            }
        }
        float2 wo = *(const float2*)(Wout + br * 64 + 2 * lane);
        float bo = bout[br];
#pragma unroll
        for (int j = 0; j < 16; j++) {
            float h0 = acc0[j] > 0.f ? acc0[j] : expm1f(acc0[j]);
            float h1 = acc1[j] > 0.f ? acc1[j] : expm1f(acc1[j]);
            float r = fmaf(h0, wo.x, h1 * wo.y);
#pragma unroll
            for (int s = 16; s > 0; s >>= 1)
                r += __shfl_xor_sync(0xffffffffu, r, s);
            if (lane == 0 && nb + j < cnt)
                out[(size_t)(base + nb + j) * 3 + br] = r + bo;
        }
    }
}

// ---------------- host orchestration: 8 launches ----------------

extern "C" void kernel_launch(void* const* d_in, const int* in_sizes, int n_in,
                              void* d_out, int out_size) {
    const float* x0 = (const float*)d_in[0];
    const float* x1 = (const float*)d_in[1];
    const float* x2 = (const float*)d_in[2];
    const int* ei0 = (const int*)d_in[3];
    const int* ei1 = (const int*)d_in[4];
    const int* ei2 = (const int*)d_in[5];
    const int*   A1r = (const int*)d_in[6];
    const int*   A1c = (const int*)d_in[7];
    const float* A1v = (const float*)d_in[8];
    const int*   A2r = (const int*)d_in[9];
    const int*   A2c = (const int*)d_in[10];
    const float* A2v = (const float*)d_in[11];
    const float* c1Wrel  = (const float*)d_in[12];
    const float* c1brel  = (const float*)d_in[13];
    const float* c1Wroot = (const float*)d_in[14];
    const float* c2Wrel  = (const float*)d_in[15];
    const float* c2brel  = (const float*)d_in[16];
    const float* c2Wroot = (const float*)d_in[17];
    const float* linW = (const float*)d_in[18];
    const float* linb = (const float*)d_in[19];
    const float* dW0   = (const float*)d_in[20];
    const float* db0   = (const float*)d_in[21];
    const float* dWout = (const float*)d_in[22];
    const float* dbout = (const float*)d_in[23];
    float* out = (float*)d_out;

    void* p;
    cudaGetSymbolAddress(&p, g_zr);  float* zr = (float*)p;
    cudaGetSymbolAddress(&p, g_h1);  float* h1 = (float*)p;
    cudaGetSymbolAddress(&p, g_h2);  float* h2 = (float*)p;
    cudaGetSymbolAddress(&p, g_e);   float* e  = (float*)p;
    float* agg6 = zr + AGG6_OFF;
    float* agg  = zr + AGG_OFF;
    float* i1b  = zr + I1_OFF;
    float* i2b  = zr + I2_OFF;

    cudaFuncSetAttribute(conv2_all, cudaFuncAttributeMaxDynamicSharedMemorySize, 131072);
    cudaFuncSetAttribute(lin_all,   cudaFuncAttributeMaxDynamicSharedMemorySize, 65536);
    cudaFuncSetAttribute(dec_gemm_kernel, cudaFuncAttributeMaxDynamicSharedMemorySize, 49152);

    zero4_kernel<<<cdiv(ZR_TOT / 4, 256), 256>>>((float4*)zr, ZR_TOT / 4);
    scatter6_all<<<cdiv(ETOT, 256), 256>>>(x0, x1, x2, ei0, ei1, ei2, agg6);
    conv1_all<<<C1_B1 + 98, 128>>>(x0, x1, x2, agg6, c1Wrel, c1brel, c1Wroot, h1);
    scatter128_all<<<cdiv(ETOT * 32, 256), 256>>>(h1, ei0, ei1, ei2, agg);
    conv2_all<<<C2_B1 + 25, 256, 131072>>>(agg, h1, c2Wrel, c2Wroot, c2brel, h2);
    lin_all<<<C2_B1 + 25, 256, 65536>>>(h2, linW, linb, e);
    interp_both<<<cdiv(2 * NNZC * 32, 256), 256>>>(e, A1r, A1c, A1v, A2r, A2c, A2v,
                                                   i1b, i2b);
    dec_gemm_kernel<<<cdiv(N0, 128), 256, 49152>>>(e, i1b, i2b, dW0, db0,
                                                   dWout, dbout, out, N0);
}

// round 4
// speedup vs baseline: 1.7118x; 1.1549x over previous
#include <cuda_runtime.h>
#include <math.h>

#define N0 50000
#define N1 12500
#define N2 3125
#define NTOT 65625            // N0+N1+N2
#define E0C 800000
#define E1C 200000
#define E2C 50000
#define ETOT 1050000
#define NNZC 200000

// node row offsets per level
#define NB1 50000
#define NB2 62500
// edge offsets
#define EB1 800000
#define EB2 1000000

// -------- fused zeroed scratch region: [agg6 | agg | i1 | i2] --------
#define AGG6_OFF 0
#define AGG_OFF  393752
#define I1_OFF   8793752
#define I2_OFF   13593752
#define ZR_TOT   18393752

__device__ float g_zr[ZR_TOT];
__device__ float g_h1[NTOT * 128];
__device__ float g_h2[NTOT * 128];
__device__ float g_e [NTOT * 96];

static inline int cdiv(int a, int b) { return (a + b - 1) / b; }

// ---------------- f32x2 packed-FMA helpers ----------------
typedef unsigned long long ull;
__device__ __forceinline__ ull pk2(float x, float y) {
    ull r; asm("mov.b64 %0, {%1, %2};" : "=l"(r) : "f"(x), "f"(y)); return r;
}
__device__ __forceinline__ ull fma2(ull a, ull b, ull c) {
    ull d; asm("fma.rn.f32x2 %0, %1, %2, %3;" : "=l"(d) : "l"(a), "l"(b), "l"(c));
    return d;
}
__device__ __forceinline__ float2 up2(ull v) {
    float2 f; asm("mov.b64 {%0, %1}, %2;" : "=f"(f.x), "=f"(f.y) : "l"(v)); return f;
}

// ---------------- kernels ----------------

__global__ void zero4_kernel(float4* __restrict__ p, int nq) {
    int i = blockIdx.x * blockDim.x + threadIdx.x;
    if (i < nq) p[i] = make_float4(0.f, 0.f, 0.f, 0.f);
}

// stage 1 aggregation, all levels: agg6[dst] += x[src] (6 feats), float2 RED
__global__ void scatter6_all(const float* __restrict__ x0, const float* __restrict__ x1,
                             const float* __restrict__ x2,
                             const int* __restrict__ ei0, const int* __restrict__ ei1,
                             const int* __restrict__ ei2,
                             float* __restrict__ agg6) {
    int e = blockIdx.x * blockDim.x + threadIdx.x;
    if (e >= ETOT) return;
    int lvl = (e >= EB1) + (e >= EB2);
    const int* ei;
    const float* x;
    int le, E, nb;
    if (lvl == 0)      { ei = ei0; x = x0; le = e;       E = E0C; nb = 0;   }
    else if (lvl == 1) { ei = ei1; x = x1; le = e - EB1; E = E1C; nb = NB1; }
    else               { ei = ei2; x = x2; le = e - EB2; E = E2C; nb = NB2; }
    int s = ei[le];
    int d = ei[E + le];
    const float2* xs = (const float2*)(x + (size_t)s * 6);
    float2* a = (float2*)(agg6 + (size_t)(nb + d) * 6);
    float2 v0 = xs[0], v1 = xs[1], v2 = xs[2];
    atomicAdd(&a[0], v0);
    atomicAdd(&a[1], v1);
    atomicAdd(&a[2], v2);
}

// conv1, all levels: h1 = relu(agg6 @ Wrel + brel + x @ Wroot); 32 nodes/block
#define C1_B0 1563
#define C1_B1 1954    // 1563 + 391
__global__ void conv1_all(const float* __restrict__ x0, const float* __restrict__ x1,
                          const float* __restrict__ x2,
                          const float* __restrict__ agg6,
                          const float* __restrict__ Wrel, const float* __restrict__ brel,
                          const float* __restrict__ Wroot, float* __restrict__ h1) {
    __shared__ float sx[32 * 6];
    __shared__ float sa[32 * 6];
    int b = blockIdx.x;
    int lvl = (b >= C1_B0) + (b >= C1_B1);
    const float* x;
    int tb, nlv, nb;
    if (lvl == 0)      { x = x0; tb = 0;     nlv = N0; nb = 0;   }
    else if (lvl == 1) { x = x1; tb = C1_B0; nlv = N1; nb = NB1; }
    else               { x = x2; tb = C1_B1; nlv = N2; nb = NB2; }
    int base = (b - tb) * 32;
    int cnt = nlv - base; if (cnt > 32) cnt = 32;
    int t = threadIdx.x;
    for (int idx = t; idx < cnt * 6; idx += 128) {
        sx[idx] = x[(size_t)base * 6 + idx];
        sa[idx] = agg6[(size_t)(nb + base) * 6 + idx];
    }
    __syncthreads();
    const float* Wr = Wrel + lvl * 6 * 128;
    const float* Wo = Wroot + lvl * 6 * 128;
    float wrel[6], wroot[6];
#pragma unroll
    for (int k = 0; k < 6; k++) { wrel[k] = Wr[k * 128 + t]; wroot[k] = Wo[k * 128 + t]; }
    float bb = brel[lvl * 128 + t];
    for (int j = 0; j < cnt; j++) {
        float acc = bb;
#pragma unroll
        for (int k = 0; k < 6; k++)
            acc = fmaf(sa[j * 6 + k], wrel[k], fmaf(sx[j * 6 + k], wroot[k], acc));
        h1[(size_t)(nb + base + j) * 128 + t] = fmaxf(acc, 0.f);
    }
}

// stage 2 aggregation, all levels: agg[dst] += h1[src] (128 feats)
// 4 edges per warp for MLP (all level boundaries are %4==0, groups never straddle)
__global__ void scatter128_all(const float* __restrict__ h1,
                               const int* __restrict__ ei0, const int* __restrict__ ei1,
                               const int* __restrict__ ei2,
                               float* __restrict__ agg) {
    int w = (blockIdx.x * blockDim.x + threadIdx.x) >> 5;
    int lane = threadIdx.x & 31;
    int e0 = w * 4;
    if (e0 >= ETOT) return;
    int lvl = (e0 >= EB1) + (e0 >= EB2);
    const int* ei;
    int le, E, nb;
    if (lvl == 0)      { ei = ei0; le = e0;       E = E0C; nb = 0;   }
    else if (lvl == 1) { ei = ei1; le = e0 - EB1; E = E1C; nb = NB1; }
    else               { ei = ei2; le = e0 - EB2; E = E2C; nb = NB2; }
    int s[4], d[4];
#pragma unroll
    for (int i = 0; i < 4; i++) { s[i] = ei[le + i]; d[i] = ei[E + le + i]; }
    float4 v[4];
#pragma unroll
    for (int i = 0; i < 4; i++)
        v[i] = *(const float4*)(h1 + (size_t)(nb + s[i]) * 128 + lane * 4);
#pragma unroll
    for (int i = 0; i < 4; i++)
        atomicAdd((float4*)(agg + (size_t)(nb + d[i]) * 128 + lane * 4), v[i]);
}

// conv2, all levels: h2 = relu(agg @ W1 + b + h1 @ W2); 128-node tiles, f32x2 math
#define C2_B0 391
#define C2_B1 489     // 391 + 98
__global__ void __launch_bounds__(256) conv2_all(
    const float* __restrict__ agg, const float* __restrict__ h1,
    const float* __restrict__ W1b, const float* __restrict__ W2b,
    const float* __restrict__ bb, float* __restrict__ h2) {
    extern __shared__ float smem[];
    float* s1 = smem;           // [128][128]
    float* s2 = smem + 16384;
    int b = blockIdx.x;
    int lvl = (b >= C2_B0) + (b >= C2_B1);
    int tb, nlv, nb;
    if (lvl == 0)      { tb = 0;     nlv = N0; nb = 0;   }
    else if (lvl == 1) { tb = C2_B0; nlv = N1; nb = NB1; }
    else               { tb = C2_B1; nlv = N2; nb = NB2; }
    int base = (b - tb) * 128;
    int cnt = nlv - base; if (cnt > 128) cnt = 128;
    size_t row0 = (size_t)(nb + base) * 128;
    int t = threadIdx.x;
    for (int idx = t * 4; idx < cnt * 128; idx += 256 * 4) {
        *(float4*)(s1 + idx) = *(const float4*)(agg + row0 + idx);
        *(float4*)(s2 + idx) = *(const float4*)(h1 + row0 + idx);
    }
    __syncthreads();
    const float* W1 = W1b + lvl * 16384;
    const float* W2 = W2b + lvl * 16384;
    int warp = t >> 5, lane = t & 31;
    int f = lane * 4;
    int nbk = warp * 16;
    float4 bias = *(const float4*)(bb + lvl * 128 + f);
    ull acc[16][2];
    ull b01 = pk2(bias.x, bias.y), b23 = pk2(bias.z, bias.w);
#pragma unroll
    for (int j = 0; j < 16; j++) { acc[j][0] = b01; acc[j][1] = b23; }
    for (int k = 0; k < 128; k++) {
        ulonglong2 w1 = *(const ulonglong2*)(W1 + k * 128 + f);
        ulonglong2 w2 = *(const ulonglong2*)(W2 + k * 128 + f);
#pragma unroll
        for (int j = 0; j < 16; j++) {
            float a1 = s1[(nbk + j) * 128 + k];
            float a2 = s2[(nbk + j) * 128 + k];
            ull a1p = pk2(a1, a1);
            ull a2p = pk2(a2, a2);
            acc[j][0] = fma2(a1p, w1.x, acc[j][0]);
            acc[j][1] = fma2(a1p, w1.y, acc[j][1]);
            acc[j][0] = fma2(a2p, w2.x, acc[j][0]);
            acc[j][1] = fma2(a2p, w2.y, acc[j][1]);
        }
    }
#pragma unroll
    for (int j = 0; j < 16; j++) {
        if (nbk + j < cnt) {
            float2 r01 = up2(acc[j][0]);
            float2 r23 = up2(acc[j][1]);
            float4 r;
            r.x = fmaxf(r01.x, 0.f);
            r.y = fmaxf(r01.y, 0.f);
            r.z = fmaxf(r23.x, 0.f);
            r.w = fmaxf(r23.y, 0.f);
            *(float4*)(h2 + row0 + (size_t)(nbk + j) * 128 + f) = r;
        }
    }
}

// lin, all levels: e = h2 @ W(128x96) + b; f32x2 math
__global__ void __launch_bounds__(256) lin_all(
    const float* __restrict__ h2, const float* __restrict__ Wb,
    const float* __restrict__ bb, float* __restrict__ e) {
    extern __shared__ float smem[];   // [128][128]
    int b = blockIdx.x;
    int lvl = (b >= C2_B0) + (b >= C2_B1);
    int tb, nlv, nb;
    if (lvl == 0)      { tb = 0;     nlv = N0; nb = 0;   }
    else if (lvl == 1) { tb = C2_B0; nlv = N1; nb = NB1; }
    else               { tb = C2_B1; nlv = N2; nb = NB2; }
    int base = (b - tb) * 128;
    int cnt = nlv - base; if (cnt > 128) cnt = 128;
    size_t row0 = (size_t)(nb + base) * 128;
    int t = threadIdx.x;
    for (int idx = t * 4; idx < cnt * 128; idx += 256 * 4)
        *(float4*)(smem + idx) = *(const float4*)(h2 + row0 + idx);
    __syncthreads();
    int warp = t >> 5, lane = t & 31;
    int f = lane * 4;
    int nbk = warp * 16;
    if (f < 96) {
        const float* W = Wb + lvl * 128 * 96;
        float4 bias = *(const float4*)(bb + lvl * 96 + f);
        ull acc[16][2];
        ull b01 = pk2(bias.x, bias.y), b23 = pk2(bias.z, bias.w);
#pragma unroll
        for (int j = 0; j < 16; j++) { acc[j][0] = b01; acc[j][1] = b23; }
        for (int k = 0; k < 128; k++) {
            ulonglong2 w = *(const ulonglong2*)(W + k * 96 + f);
#pragma unroll
            for (int j = 0; j < 16; j++) {
                float a = smem[(nbk + j) * 128 + k];
                ull ap = pk2(a, a);
                acc[j][0] = fma2(ap, w.x, acc[j][0]);
                acc[j][1] = fma2(ap, w.y, acc[j][1]);
            }
        }
#pragma unroll
        for (int j = 0; j < 16; j++) {
            if (nbk + j < cnt) {
                float2 r01 = up2(acc[j][0]);
                float2 r23 = up2(acc[j][1]);
                float4 r = make_float4(r01.x, r01.y, r23.x, r23.y);
                *(float4*)(e + (size_t)(nb + base + nbk + j) * 96 + f) = r;
            }
        }
    }
}

// both interpolations fused; 4 nnz per warp (NNZC %4 == 0), lanes 0..23
__global__ void interp_both(const float* __restrict__ e,
                            const int* __restrict__ A1r, const int* __restrict__ A1c,
                            const float* __restrict__ A1v,
                            const int* __restrict__ A2r, const int* __restrict__ A2c,
                            const float* __restrict__ A2v,
                            float* __restrict__ i1, float* __restrict__ i2) {
    int w = (blockIdx.x * blockDim.x + threadIdx.x) >> 5;
    int lane = threadIdx.x & 31;
    int q0 = w * 4;
    if (q0 >= 2 * NNZC) return;
    const int* Ar; const int* Ac; const float* Av; const float* ebase; float* dst; int off;
    if (q0 < NNZC) { Ar = A1r; Ac = A1c; Av = A1v;
                     ebase = e + (size_t)NB1 * 96; dst = i1; off = q0; }
    else           { Ar = A2r; Ac = A2c; Av = A2v;
                     ebase = e + (size_t)NB2 * 96; dst = i2; off = q0 - NNZC; }
    int r[4], c[4]; float v[4];
#pragma unroll
    for (int i = 0; i < 4; i++) { r[i] = Ar[off + i]; c[i] = Ac[off + i]; v[i] = Av[off + i]; }
    if (lane < 24) {
        float4 x[4];
#pragma unroll
        for (int i = 0; i < 4; i++)
            x[i] = *(const float4*)(ebase + (size_t)c[i] * 96 + lane * 4);
#pragma unroll
        for (int i = 0; i < 4; i++) {
            float4 y = make_float4(x[i].x * v[i], x[i].y * v[i], x[i].z * v[i], x[i].w * v[i]);
            atomicAdd((float4*)(dst + (size_t)r[i] * 96 + lane * 4), y);
        }
    }
}

// decoder as GEMM: tile 128 nodes; per branch stage [128][96] smem; f32x2 math
__global__ void __launch_bounds__(256) dec_gemm_kernel(
    const float* __restrict__ e0, const float* __restrict__ i1,
    const float* __restrict__ i2,
    const float* __restrict__ W0, const float* __restrict__ b0,
    const float* __restrict__ Wout, const float* __restrict__ bout,
    float* __restrict__ out, int n) {
    extern __shared__ float sin_[]; // [128][96]
    int base = blockIdx.x * 128;
    int cnt = n - base; if (cnt > 128) cnt = 128;
    int t = threadIdx.x;
    int lane = t & 31;
    int nb = (t >> 5) * 16;
#pragma unroll
    for (int br = 0; br < 3; br++) {
        __syncthreads();
        for (int idx = t; idx < cnt * 24; idx += 256) {
            int node = idx / 24, q = idx % 24;
            const float* srcp =
                (q < 8)  ? (e0 + (size_t)(base + node) * 96 + br * 32 + q * 4) :
                (q < 16) ? (i1 + (size_t)(base + node) * 96 + br * 32 + (q - 8) * 4) :
                           (i2 + (size_t)(base + node) * 96 + br * 32 + (q - 16) * 4);
            *(float4*)(sin_ + node * 96 + q * 4) = *(const float4*)srcp;
        }
        __syncthreads();
        const float* W = W0 + br * 96 * 64;
        ull bb = *(const ull*)(b0 + br * 64 + 2 * lane);
        ull accp[16];
#pragma unroll
        for (int j = 0; j < 16; j++) accp[j] = bb;
        for (int k = 0; k < 96; k += 4) {
            ull w0 = *(const ull*)(W + (k + 0) * 64 + 2 * lane);
            ull w1 = *(const ull*)(W + (k + 1) * 64 + 2 * lane);
            ull w2 = *(const ull*)(W + (k + 2) * 64 + 2 * lane);
            ull w3 = *(const ull*)(W + (k + 3) * 64 + 2 * lane);
#pragma unroll
            for (int j = 0; j < 16; j++) {
                float4 a = *(const float4*)(sin_ + (nb + j) * 96 + k);
                accp[j] = fma2(pk2(a.x, a.x), w0, accp[j]);
                accp[j] = fma2(pk2(a.y, a.y), w1, accp[j]);
                accp[j] = fma2(pk2(a.z, a.z), w2, accp[j]);
                accp[j] = fma2(pk2(a.w, a.w), w3, accp[j]);
            }
        }
        float2 wo = *(const float2*)(Wout + br * 64 + 2 * lane);
        float bo = bout[br];
#pragma unroll
        for (int j = 0; j < 16; j++) {
            float2 h = up2(accp[j]);
            float h0 = h.x > 0.f ? h.x : expm1f(h.x);
            float h1 = h.y > 0.f ? h.y : expm1f(h.y);
            float r = fmaf(h0, wo.x, h1 * wo.y);
#pragma unroll
            for (int s = 16; s > 0; s >>= 1)
                r += __shfl_xor_sync(0xffffffffu, r, s);
            if (lane == 0 && nb + j < cnt)
                out[(size_t)(base + nb + j) * 3 + br] = r + bo;
        }
    }
}

// ---------------- host orchestration: 8 launches ----------------

extern "C" void kernel_launch(void* const* d_in, const int* in_sizes, int n_in,
                              void* d_out, int out_size) {
    const float* x0 = (const float*)d_in[0];
    const float* x1 = (const float*)d_in[1];
    const float* x2 = (const float*)d_in[2];
    const int* ei0 = (const int*)d_in[3];
    const int* ei1 = (const int*)d_in[4];
    const int* ei2 = (const int*)d_in[5];
    const int*   A1r = (const int*)d_in[6];
    const int*   A1c = (const int*)d_in[7];
    const float* A1v = (const float*)d_in[8];
    const int*   A2r = (const int*)d_in[9];
    const int*   A2c = (const int*)d_in[10];
    const float* A2v = (const float*)d_in[11];
    const float* c1Wrel  = (const float*)d_in[12];
    const float* c1brel  = (const float*)d_in[13];
    const float* c1Wroot = (const float*)d_in[14];
    const float* c2Wrel  = (const float*)d_in[15];
    const float* c2brel  = (const float*)d_in[16];
    const float* c2Wroot = (const float*)d_in[17];
    const float* linW = (const float*)d_in[18];
    const float* linb = (const float*)d_in[19];
    const float* dW0   = (const float*)d_in[20];
    const float* db0   = (const float*)d_in[21];
    const float* dWout = (const float*)d_in[22];
    const float* dbout = (const float*)d_in[23];
    float* out = (float*)d_out;

    void* p;
    cudaGetSymbolAddress(&p, g_zr);  float* zr = (float*)p;
    cudaGetSymbolAddress(&p, g_h1);  float* h1 = (float*)p;
    cudaGetSymbolAddress(&p, g_h2);  float* h2 = (float*)p;
    cudaGetSymbolAddress(&p, g_e);   float* e  = (float*)p;
    float* agg6 = zr + AGG6_OFF;
    float* agg  = zr + AGG_OFF;
    float* i1b  = zr + I1_OFF;
    float* i2b  = zr + I2_OFF;

    cudaFuncSetAttribute(conv2_all, cudaFuncAttributeMaxDynamicSharedMemorySize, 131072);
    cudaFuncSetAttribute(lin_all,   cudaFuncAttributeMaxDynamicSharedMemorySize, 65536);
    cudaFuncSetAttribute(dec_gemm_kernel, cudaFuncAttributeMaxDynamicSharedMemorySize, 49152);

    zero4_kernel<<<cdiv(ZR_TOT / 4, 256), 256>>>((float4*)zr, ZR_TOT / 4);
    scatter6_all<<<cdiv(ETOT, 256), 256>>>(x0, x1, x2, ei0, ei1, ei2, agg6);
    conv1_all<<<C1_B1 + 98, 128>>>(x0, x1, x2, agg6, c1Wrel, c1brel, c1Wroot, h1);
    scatter128_all<<<cdiv((ETOT / 4) * 32, 256), 256>>>(h1, ei0, ei1, ei2, agg);
    conv2_all<<<C2_B1 + 25, 256, 131072>>>(agg, h1, c2Wrel, c2Wroot, c2brel, h2);
    lin_all<<<C2_B1 + 25, 256, 65536>>>(h2, linW, linb, e);
    interp_both<<<cdiv((2 * NNZC / 4) * 32, 256), 256>>>(e, A1r, A1c, A1v,
                                                         A2r, A2c, A2v, i1b, i2b);
    dec_gemm_kernel<<<cdiv(N0, 128), 256, 49152>>>(e, i1b, i2b, dW0, db0,
                                                   dWout, dbout, out, N0);
}

// round 5
// speedup vs baseline: 1.9385x; 1.1324x over previous
#include <cuda_runtime.h>
#include <math.h>

#define N0 50000
#define N1 12500
#define N2 3125
#define NTOT 65625            // N0+N1+N2
#define E0C 800000
#define E1C 200000
#define E2C 50000
#define ETOT 1050000
#define NNZC 200000

// node row offsets per level
#define NB1 50000
#define NB2 62500
// edge offsets
#define EB1 800000
#define EB2 1000000

// -------- fused zeroed scratch region: [agg6 | agg | i1 | i2] --------
#define AGG6_OFF 0
#define AGG_OFF  393752
#define I1_OFF   8793752
#define I2_OFF   13593752
#define ZR_TOT   18393752

__device__ float g_zr[ZR_TOT];
__device__ float g_h1[NTOT * 128];
__device__ float g_e [NTOT * 96];
// pair-interleaved (along k) weight copies
__device__ float g_w1t[3 * 16384];
__device__ float g_w2t[3 * 16384];
__device__ float g_lint[3 * 12288];
__device__ float g_dect[3 * 6144];

static inline int cdiv(int a, int b) { return (a + b - 1) / b; }

// ---------------- f32x2 helpers ----------------
typedef unsigned long long ull;
__device__ __forceinline__ ull pk2(float x, float y) {
    ull r; asm("mov.b64 %0, {%1, %2};" : "=l"(r) : "f"(x), "f"(y)); return r;
}
__device__ __forceinline__ ull fma2(ull a, ull b, ull c) {
    ull d; asm("fma.rn.f32x2 %0, %1, %2, %3;" : "=l"(d) : "l"(a), "l"(b), "l"(c));
    return d;
}
__device__ __forceinline__ float2 up2(ull v) {
    float2 f; asm("mov.b64 {%0, %1}, %2;" : "=f"(f.x), "=f"(f.y) : "l"(v)); return f;
}
__device__ __forceinline__ float hsum2(ull v) { float2 f = up2(v); return f.x + f.y; }

// ---------------- weight repack: Wt[k/2][f][2] = (W[2m][f], W[2m+1][f]) ----------------
__global__ void repack_kernel(const float* __restrict__ W1, const float* __restrict__ W2,
                              const float* __restrict__ linW, const float* __restrict__ decW,
                              float* __restrict__ w1t, float* __restrict__ w2t,
                              float* __restrict__ lint, float* __restrict__ dect) {
    int i = blockIdx.x * blockDim.x + threadIdx.x;
    if (i < 24576) {                       // 3 lvl x 64 m x 128 f
        int lvl = i / 8192, r = i % 8192, m = r / 128, f = r % 128;
        int src = lvl * 16384, dst = lvl * 16384 + m * 256 + f * 2;
        w1t[dst]     = W1[src + (2 * m) * 128 + f];
        w1t[dst + 1] = W1[src + (2 * m + 1) * 128 + f];
        w2t[dst]     = W2[src + (2 * m) * 128 + f];
        w2t[dst + 1] = W2[src + (2 * m + 1) * 128 + f];
    } else if (i < 24576 + 18432) {        // 3 lvl x 64 m x 96 f
        int q = i - 24576;
        int lvl = q / 6144, r = q % 6144, m = r / 96, f = r % 96;
        lint[lvl * 12288 + m * 192 + f * 2]     = linW[lvl * 12288 + (2 * m) * 96 + f];
        lint[lvl * 12288 + m * 192 + f * 2 + 1] = linW[lvl * 12288 + (2 * m + 1) * 96 + f];
    } else if (i < 24576 + 18432 + 9216) { // 3 br x 48 m x 64 h
        int q = i - 43008;
        int br = q / 3072, r = q % 3072, m = r / 64, h = r % 64;
        dect[br * 6144 + m * 128 + h * 2]     = decW[br * 6144 + (2 * m) * 64 + h];
        dect[br * 6144 + m * 128 + h * 2 + 1] = decW[br * 6144 + (2 * m + 1) * 64 + h];
    }
}

// ---------------- kernels ----------------

__global__ void zero4_kernel(float4* __restrict__ p, int nq) {
    int i = blockIdx.x * blockDim.x + threadIdx.x;
    if (i < nq) p[i] = make_float4(0.f, 0.f, 0.f, 0.f);
}

// stage 1 aggregation: agg6[dst] += x[src] (6 feats), float2 RED
__global__ void scatter6_all(const float* __restrict__ x0, const float* __restrict__ x1,
                             const float* __restrict__ x2,
                             const int* __restrict__ ei0, const int* __restrict__ ei1,
                             const int* __restrict__ ei2,
                             float* __restrict__ agg6) {
    int e = blockIdx.x * blockDim.x + threadIdx.x;
    if (e >= ETOT) return;
    int lvl = (e >= EB1) + (e >= EB2);
    const int* ei;
    const float* x;
    int le, E, nb;
    if (lvl == 0)      { ei = ei0; x = x0; le = e;       E = E0C; nb = 0;   }
    else if (lvl == 1) { ei = ei1; x = x1; le = e - EB1; E = E1C; nb = NB1; }
    else               { ei = ei2; x = x2; le = e - EB2; E = E2C; nb = NB2; }
    int s = ei[le];
    int d = ei[E + le];
    const float2* xs = (const float2*)(x + (size_t)s * 6);
    float2* a = (float2*)(agg6 + (size_t)(nb + d) * 6);
    float2 v0 = xs[0], v1 = xs[1], v2 = xs[2];
    atomicAdd(&a[0], v0);
    atomicAdd(&a[1], v1);
    atomicAdd(&a[2], v2);
}

// conv1, all levels: h1 = relu(agg6 @ Wrel + brel + x @ Wroot); 32 nodes/block
#define C1_B0 1563
#define C1_B1 1954    // 1563 + 391
__global__ void conv1_all(const float* __restrict__ x0, const float* __restrict__ x1,
                          const float* __restrict__ x2,
                          const float* __restrict__ agg6,
                          const float* __restrict__ Wrel, const float* __restrict__ brel,
                          const float* __restrict__ Wroot, float* __restrict__ h1) {
    __shared__ float sx[32 * 6];
    __shared__ float sa[32 * 6];
    int b = blockIdx.x;
    int lvl = (b >= C1_B0) + (b >= C1_B1);
    const float* x;
    int tb, nlv, nb;
    if (lvl == 0)      { x = x0; tb = 0;     nlv = N0; nb = 0;   }
    else if (lvl == 1) { x = x1; tb = C1_B0; nlv = N1; nb = NB1; }
    else               { x = x2; tb = C1_B1; nlv = N2; nb = NB2; }
    int base = (b - tb) * 32;
    int cnt = nlv - base; if (cnt > 32) cnt = 32;
    int t = threadIdx.x;
    for (int idx = t; idx < cnt * 6; idx += 128) {
        sx[idx] = x[(size_t)base * 6 + idx];
        sa[idx] = agg6[(size_t)(nb + base) * 6 + idx];
    }
    __syncthreads();
    const float* Wr = Wrel + lvl * 6 * 128;
    const float* Wo = Wroot + lvl * 6 * 128;
    float wrel[6], wroot[6];
#pragma unroll
    for (int k = 0; k < 6; k++) { wrel[k] = Wr[k * 128 + t]; wroot[k] = Wo[k * 128 + t]; }
    float bb = brel[lvl * 128 + t];
    for (int j = 0; j < cnt; j++) {
        float acc = bb;
#pragma unroll
        for (int k = 0; k < 6; k++)
            acc = fmaf(sa[j * 6 + k], wrel[k], fmaf(sx[j * 6 + k], wroot[k], acc));
        h1[(size_t)(nb + base + j) * 128 + t] = fmaxf(acc, 0.f);
    }
}

// stage 2 aggregation: agg[dst] += h1[src] (128 feats); 4 edges per warp
__global__ void scatter128_all(const float* __restrict__ h1,
                               const int* __restrict__ ei0, const int* __restrict__ ei1,
                               const int* __restrict__ ei2,
                               float* __restrict__ agg) {
    int w = (blockIdx.x * blockDim.x + threadIdx.x) >> 5;
    int lane = threadIdx.x & 31;
    int e0 = w * 4;
    if (e0 >= ETOT) return;
    int lvl = (e0 >= EB1) + (e0 >= EB2);
    const int* ei;
    int le, E, nb;
    if (lvl == 0)      { ei = ei0; le = e0;       E = E0C; nb = 0;   }
    else if (lvl == 1) { ei = ei1; le = e0 - EB1; E = E1C; nb = NB1; }
    else               { ei = ei2; le = e0 - EB2; E = E2C; nb = NB2; }
    int s[4], d[4];
#pragma unroll
    for (int i = 0; i < 4; i++) { s[i] = ei[le + i]; d[i] = ei[E + le + i]; }
    float4 v[4];
#pragma unroll
    for (int i = 0; i < 4; i++)
        v[i] = *(const float4*)(h1 + (size_t)(nb + s[i]) * 128 + lane * 4);
#pragma unroll
    for (int i = 0; i < 4; i++)
        atomicAdd((float4*)(agg + (size_t)(nb + d[i]) * 128 + lane * 4), v[i]);
}

// fused conv2 + lin, all levels; 64-node tiles, k-pair f32x2, zero packs.
// h2 = relu(agg @ W1 + b + h1 @ W2) kept in smem (warp-local), then e = h2 @ Wlin + blin
#define CL_B0 782
#define CL_B1 978     // 782 + 196; +49 for level 2 -> 1027 total
__global__ void __launch_bounds__(256, 2) conv2lin_all(
    const float* __restrict__ agg, const float* __restrict__ h1,
    const float* __restrict__ w1t, const float* __restrict__ w2t,
    const float* __restrict__ c2b,
    const float* __restrict__ lint, const float* __restrict__ linb,
    float* __restrict__ e) {
    extern __shared__ float smem[];
    float* s1 = smem;           // [64][128]
    float* s2 = smem + 8192;    // [64][128]
    int b = blockIdx.x;
    int lvl = (b >= CL_B0) + (b >= CL_B1);
    int tb, nlv, nb0;
    if (lvl == 0)      { tb = 0;     nlv = N0; nb0 = 0;   }
    else if (lvl == 1) { tb = CL_B0; nlv = N1; nb0 = NB1; }
    else               { tb = CL_B1; nlv = N2; nb0 = NB2; }
    int base = (b - tb) * 64;
    int cnt = nlv - base; if (cnt > 64) cnt = 64;
    size_t row0 = (size_t)(nb0 + base) * 128;
    int t = threadIdx.x;
    for (int idx = t * 4; idx < cnt * 128; idx += 1024) {
        *(float4*)(s1 + idx) = *(const float4*)(agg + row0 + idx);
        *(float4*)(s2 + idx) = *(const float4*)(h1 + row0 + idx);
    }
    __syncthreads();
    int lane = t & 31;
    int f = lane * 4;
    int nbk = (t >> 5) * 8;
    const float* W1 = w1t + lvl * 16384;
    const float* W2 = w2t + lvl * 16384;
    float4 bias = *(const float4*)(c2b + lvl * 128 + f);
    ull acc[8][4];
#pragma unroll
    for (int j = 0; j < 8; j++) {
        acc[j][0] = pk2(bias.x, 0.f);
        acc[j][1] = pk2(bias.y, 0.f);
        acc[j][2] = pk2(bias.z, 0.f);
        acc[j][3] = pk2(bias.w, 0.f);
    }
    for (int m = 0; m < 64; m++) {
        ulonglong2 w1lo = *(const ulonglong2*)(W1 + m * 256 + f * 2);
        ulonglong2 w1hi = *(const ulonglong2*)(W1 + m * 256 + f * 2 + 4);
        ulonglong2 w2lo = *(const ulonglong2*)(W2 + m * 256 + f * 2);
        ulonglong2 w2hi = *(const ulonglong2*)(W2 + m * 256 + f * 2 + 4);
#pragma unroll
        for (int j = 0; j < 8; j++) {
            ull a1 = *(const ull*)(s1 + (nbk + j) * 128 + 2 * m);
            ull a2 = *(const ull*)(s2 + (nbk + j) * 128 + 2 * m);
            acc[j][0] = fma2(a1, w1lo.x, acc[j][0]);
            acc[j][1] = fma2(a1, w1lo.y, acc[j][1]);
            acc[j][2] = fma2(a1, w1hi.x, acc[j][2]);
            acc[j][3] = fma2(a1, w1hi.y, acc[j][3]);
            acc[j][0] = fma2(a2, w2lo.x, acc[j][0]);
            acc[j][1] = fma2(a2, w2lo.y, acc[j][1]);
            acc[j][2] = fma2(a2, w2hi.x, acc[j][2]);
            acc[j][3] = fma2(a2, w2hi.y, acc[j][3]);
        }
    }
    // h2 = relu(lo+hi) back into s1 (each warp touches only its own 8 rows)
#pragma unroll
    for (int j = 0; j < 8; j++) {
        float4 r;
        r.x = fmaxf(hsum2(acc[j][0]), 0.f);
        r.y = fmaxf(hsum2(acc[j][1]), 0.f);
        r.z = fmaxf(hsum2(acc[j][2]), 0.f);
        r.w = fmaxf(hsum2(acc[j][3]), 0.f);
        *(float4*)(s1 + (nbk + j) * 128 + f) = r;
    }
    __syncwarp();
    // lin epilogue: e = h2 @ Wlin(128x96) + blin; lanes 0..23 active
    if (f < 96) {
        const float* WL = lint + lvl * 12288;
        float4 lb = *(const float4*)(linb + lvl * 96 + f);
        ull acc2[8][4];
#pragma unroll
        for (int j = 0; j < 8; j++) {
            acc2[j][0] = pk2(lb.x, 0.f);
            acc2[j][1] = pk2(lb.y, 0.f);
            acc2[j][2] = pk2(lb.z, 0.f);
            acc2[j][3] = pk2(lb.w, 0.f);
        }
        for (int m = 0; m < 64; m++) {
            ulonglong2 wlo = *(const ulonglong2*)(WL + m * 192 + f * 2);
            ulonglong2 whi = *(const ulonglong2*)(WL + m * 192 + f * 2 + 4);
#pragma unroll
            for (int j = 0; j < 8; j++) {
                ull a = *(const ull*)(s1 + (nbk + j) * 128 + 2 * m);
                acc2[j][0] = fma2(a, wlo.x, acc2[j][0]);
                acc2[j][1] = fma2(a, wlo.y, acc2[j][1]);
                acc2[j][2] = fma2(a, whi.x, acc2[j][2]);
                acc2[j][3] = fma2(a, whi.y, acc2[j][3]);
            }
        }
#pragma unroll
        for (int j = 0; j < 8; j++) {
            if (nbk + j < cnt) {
                float4 r = make_float4(hsum2(acc2[j][0]), hsum2(acc2[j][1]),
                                       hsum2(acc2[j][2]), hsum2(acc2[j][3]));
                *(float4*)(e + (size_t)(nb0 + base + nbk + j) * 96 + f) = r;
            }
        }
    }
}

// both interpolations fused; 4 nnz per warp, lanes 0..23
__global__ void interp_both(const float* __restrict__ e,
                            const int* __restrict__ A1r, const int* __restrict__ A1c,
                            const float* __restrict__ A1v,
                            const int* __restrict__ A2r, const int* __restrict__ A2c,
                            const float* __restrict__ A2v,
                            float* __restrict__ i1, float* __restrict__ i2) {
    int w = (blockIdx.x * blockDim.x + threadIdx.x) >> 5;
    int lane = threadIdx.x & 31;
    int q0 = w * 4;
    if (q0 >= 2 * NNZC) return;
    const int* Ar; const int* Ac; const float* Av; const float* ebase; float* dst; int off;
    if (q0 < NNZC) { Ar = A1r; Ac = A1c; Av = A1v;
                     ebase = e + (size_t)NB1 * 96; dst = i1; off = q0; }
    else           { Ar = A2r; Ac = A2c; Av = A2v;
                     ebase = e + (size_t)NB2 * 96; dst = i2; off = q0 - NNZC; }
    int r[4], c[4]; float v[4];
#pragma unroll
    for (int i = 0; i < 4; i++) { r[i] = Ar[off + i]; c[i] = Ac[off + i]; v[i] = Av[off + i]; }
    if (lane < 24) {
        float4 x[4];
#pragma unroll
        for (int i = 0; i < 4; i++)
            x[i] = *(const float4*)(ebase + (size_t)c[i] * 96 + lane * 4);
#pragma unroll
        for (int i = 0; i < 4; i++) {
            float4 y = make_float4(x[i].x * v[i], x[i].y * v[i], x[i].z * v[i], x[i].w * v[i]);
            atomicAdd((float4*)(dst + (size_t)r[i] * 96 + lane * 4), y);
        }
    }
}

// decoder GEMM: 128-node tiles; k-pair f32x2 with pair-packed weights (zero packs)
__global__ void __launch_bounds__(256) dec_gemm_kernel(
    const float* __restrict__ e0, const float* __restrict__ i1,
    const float* __restrict__ i2,
    const float* __restrict__ dect, const float* __restrict__ b0,
    const float* __restrict__ Wout, const float* __restrict__ bout,
    float* __restrict__ out, int n) {
    extern __shared__ float sin_[]; // [128][96]
    int base = blockIdx.x * 128;
    int cnt = n - base; if (cnt > 128) cnt = 128;
    int t = threadIdx.x;
    int lane = t & 31;
    int nb = (t >> 5) * 16;
#pragma unroll
    for (int br = 0; br < 3; br++) {
        __syncthreads();
        for (int idx = t; idx < cnt * 24; idx += 256) {
            int node = idx / 24, q = idx % 24;
            const float* srcp =
                (q < 8)  ? (e0 + (size_t)(base + node) * 96 + br * 32 + q * 4) :
                (q < 16) ? (i1 + (size_t)(base + node) * 96 + br * 32 + (q - 8) * 4) :
                           (i2 + (size_t)(base + node) * 96 + br * 32 + (q - 16) * 4);
            *(float4*)(sin_ + node * 96 + q * 4) = *(const float4*)srcp;
        }
        __syncthreads();
        const float* W = dect + br * 6144;
        float2 bb = *(const float2*)(b0 + br * 64 + 2 * lane);
        ull acc0[16], acc1[16];
        ull b0p = pk2(bb.x, 0.f), b1p = pk2(bb.y, 0.f);
#pragma unroll
        for (int j = 0; j < 16; j++) { acc0[j] = b0p; acc1[j] = b1p; }
        for (int m = 0; m < 48; m++) {
            // (W[2m][h0], W[2m+1][h0]) , (W[2m][h0+1], W[2m+1][h0+1])
            ulonglong2 w = *(const ulonglong2*)(W + m * 128 + lane * 4);
#pragma unroll
            for (int j = 0; j < 16; j++) {
                ull a = *(const ull*)(sin_ + (nb + j) * 96 + 2 * m);
                acc0[j] = fma2(a, w.x, acc0[j]);
                acc1[j] = fma2(a, w.y, acc1[j]);
            }
        }
        float2 wo = *(const float2*)(Wout + br * 64 + 2 * lane);
        float bo = bout[br];
#pragma unroll
        for (int j = 0; j < 16; j++) {
            float h0 = hsum2(acc0[j]);
            float h1 = hsum2(acc1[j]);
            h0 = h0 > 0.f ? h0 : expm1f(h0);
            h1 = h1 > 0.f ? h1 : expm1f(h1);
            float r = fmaf(h0, wo.x, h1 * wo.y);
#pragma unroll
            for (int s = 16; s > 0; s >>= 1)
                r += __shfl_xor_sync(0xffffffffu, r, s);
            if (lane == 0 && nb + j < cnt)
                out[(size_t)(base + nb + j) * 3 + br] = r + bo;
        }
    }
}

// ---------------- host orchestration: 8 launches ----------------

extern "C" void kernel_launch(void* const* d_in, const int* in_sizes, int n_in,
                              void* d_out, int out_size) {
    const float* x0 = (const float*)d_in[0];
    const float* x1 = (const float*)d_in[1];
    const float* x2 = (const float*)d_in[2];
    const int* ei0 = (const int*)d_in[3];
    const int* ei1 = (const int*)d_in[4];
    const int* ei2 = (const int*)d_in[5];
    const int*   A1r = (const int*)d_in[6];
    const int*   A1c = (const int*)d_in[7];
    const float* A1v = (const float*)d_in[8];
    const int*   A2r = (const int*)d_in[9];
    const int*   A2c = (const int*)d_in[10];
    const float* A2v = (const float*)d_in[11];
    const float* c1Wrel  = (const float*)d_in[12];
    const float* c1brel  = (const float*)d_in[13];
    const float* c1Wroot = (const float*)d_in[14];
    const float* c2Wrel  = (const float*)d_in[15];
    const float* c2brel  = (const float*)d_in[16];
    const float* c2Wroot = (const float*)d_in[17];
    const float* linW = (const float*)d_in[18];
    const float* linb = (const float*)d_in[19];
    const float* dW0   = (const float*)d_in[20];
    const float* db0   = (const float*)d_in[21];
    const float* dWout = (const float*)d_in[22];
    const float* dbout = (const float*)d_in[23];
    float* out = (float*)d_out;

    void* p;
    cudaGetSymbolAddress(&p, g_zr);   float* zr   = (float*)p;
    cudaGetSymbolAddress(&p, g_h1);   float* h1   = (float*)p;
    cudaGetSymbolAddress(&p, g_e);    float* e    = (float*)p;
    cudaGetSymbolAddress(&p, g_w1t);  float* w1t  = (float*)p;
    cudaGetSymbolAddress(&p, g_w2t);  float* w2t  = (float*)p;
    cudaGetSymbolAddress(&p, g_lint); float* lint = (float*)p;
    cudaGetSymbolAddress(&p, g_dect); float* dect = (float*)p;
    float* agg6 = zr + AGG6_OFF;
    float* agg  = zr + AGG_OFF;
    float* i1b  = zr + I1_OFF;
    float* i2b  = zr + I2_OFF;

    cudaFuncSetAttribute(conv2lin_all, cudaFuncAttributeMaxDynamicSharedMemorySize, 65536);
    cudaFuncSetAttribute(dec_gemm_kernel, cudaFuncAttributeMaxDynamicSharedMemorySize, 49152);

    repack_kernel<<<cdiv(52224, 256), 256>>>(c2Wrel, c2Wroot, linW, dW0,
                                             w1t, w2t, lint, dect);
    zero4_kernel<<<cdiv(ZR_TOT / 4, 256), 256>>>((float4*)zr, ZR_TOT / 4);
    scatter6_all<<<cdiv(ETOT, 256), 256>>>(x0, x1, x2, ei0, ei1, ei2, agg6);
    conv1_all<<<C1_B1 + 98, 128>>>(x0, x1, x2, agg6, c1Wrel, c1brel, c1Wroot, h1);
    scatter128_all<<<cdiv((ETOT / 4) * 32, 256), 256>>>(h1, ei0, ei1, ei2, agg);
    conv2lin_all<<<CL_B1 + 49, 256, 65536>>>(agg, h1, w1t, w2t, c2brel,
                                             lint, linb, e);
    interp_both<<<cdiv((2 * NNZC / 4) * 32, 256), 256>>>(e, A1r, A1c, A1v,
                                                         A2r, A2c, A2v, i1b, i2b);
    dec_gemm_kernel<<<cdiv(N0, 128), 256, 49152>>>(e, i1b, i2b, dect, db0,
                                                   dWout, dbout, out, N0);
}